// round 12
// baseline (speedup 1.0000x reference)
#include <cuda_runtime.h>
#include <math.h>

// Problem constants
#define BB    4
#define SS    128
#define LL    2304          // SEQ + 2S
#define DIN   512
#define DK    64
#define NROW  (BB*LL)       // 9216
#define MIDLO SS            // 128
#define MIDHI (LL-SS)       // 2176
#define SCALE 0.125f        // 1/sqrt(64)

// Scratch: projected Q/K/V for all rows
__device__ float g_Q[NROW*DK];
__device__ float g_K[NROW*DK];
__device__ float g_V[NROW*DK];

// ---------------------------------------------------------------------------
// Kernel 1: LayerNorm + QKV projection. 16 rows per CTA, float4 xn reads.
// ---------------------------------------------------------------------------
#define RPC 16
__global__ __launch_bounds__(256) void ln_proj_kernel(
    const float* __restrict__ x,
    const float* __restrict__ Wq,  const float* __restrict__ Wk,  const float* __restrict__ Wv,
    const float* __restrict__ Wqs, const float* __restrict__ Wks, const float* __restrict__ Wvs,
    const float* __restrict__ Wqe, const float* __restrict__ Wke, const float* __restrict__ Wve,
    const float* __restrict__ lg,  const float* __restrict__ lb,
    const float* __restrict__ lsg, const float* __restrict__ lsb,
    const float* __restrict__ leg, const float* __restrict__ leb)
{
    __shared__ float xn[RPC*DIN];                // 32 KB normalized rows
    const int tid  = threadIdx.x;
    const int w    = tid >> 5;
    const int lane = tid & 31;
    const int r0   = blockIdx.x * RPC;           // segment bounds are %16 == 0
    const int rloc = r0 % LL;
    const int seg  = (rloc < SS) ? 1 : (rloc >= MIDHI ? 2 : 0);

    const float* g  = seg==0 ? lg : (seg==1 ? lsg : leg);
    const float* be = seg==0 ? lb : (seg==1 ? lsb : leb);

    // --- LayerNorm: warp w handles rows 2w, 2w+1 ---
    #pragma unroll
    for (int rr = 0; rr < 2; rr++) {
        const int rl = w*2 + rr;
        const float* xr = x + (size_t)(r0 + rl) * DIN;
        float s = 0.f, s2 = 0.f;
        for (int i = lane; i < DIN; i += 32) { float v = xr[i]; s += v; s2 += v*v; }
        #pragma unroll
        for (int o = 16; o; o >>= 1) {
            s  += __shfl_xor_sync(0xffffffffu, s,  o);
            s2 += __shfl_xor_sync(0xffffffffu, s2, o);
        }
        const float mean = s * (1.0f/DIN);
        const float var  = s2 * (1.0f/DIN) - mean*mean;
        const float rstd = rsqrtf(var + 1e-5f);
        for (int i = lane; i < DIN; i += 32)
            xn[rl*DIN + i] = (xr[i] - mean) * rstd * g[i] + be[i];
    }
    __syncthreads();

    // --- Projections: 192 output columns, 16 rows each ---
    if (tid < 192) {
        const float* W; float* dst; int col;
        if (tid < 64)       { W = seg==0 ? Wq : (seg==1 ? Wqs : Wqe); dst = g_Q; col = tid; }
        else if (tid < 128) { W = seg==0 ? Wk : (seg==1 ? Wks : Wke); dst = g_K; col = tid - 64; }
        else                { W = seg==0 ? Wv : (seg==1 ? Wvs : Wve); dst = g_V; col = tid - 128; }

        float acc[RPC];
        #pragma unroll
        for (int r = 0; r < RPC; r++) acc[r] = 0.f;

        for (int i4 = 0; i4 < DIN/4; i4++) {
            const int i = i4 * 4;
            const float w0 = W[(i+0)*DK + col];   // coalesced across lanes
            const float w1 = W[(i+1)*DK + col];
            const float w2 = W[(i+2)*DK + col];
            const float w3 = W[(i+3)*DK + col];
            #pragma unroll
            for (int r = 0; r < RPC; r++) {
                const float4 x4 = *(const float4*)&xn[r*DIN + i];   // LDS.128 broadcast
                acc[r] += x4.x*w0 + x4.y*w1 + x4.z*w2 + x4.w*w3;
            }
        }
        #pragma unroll
        for (int r = 0; r < RPC; r++) dst[(size_t)(r0 + r)*DK + col] = acc[r];
    }
}

// ---------------------------------------------------------------------------
// Kernel 2: fused CoPE-gated causal attention.
//  - CTA: 32 q rows, 512 threads, 16 warps; warp = 2 q rows (doubles total
//    resident warps vs 4-row warps: 4608 warps -> ~31/SM, the occupancy that
//    launch_bounds could never create because warp count was grid-structural).
//  - k-tiles of 32 DESCENDING; saturation split (pos==127 exactly after the
//    suffix sum crosses 127 -> bias = c127 const); fixed-shift softmax.
// ---------------------------------------------------------------------------
#define KROW 68                       // padded K row (floats): conflict-free LDS.128
__global__ __launch_bounds__(512, 2) void attn_kernel(
    const float* __restrict__ cope,   // [64][128] row-major
    float* __restrict__ out)          // [B][L][64]
{
    __shared__ float Ksm[32*KROW];    // K tile [kk][d], padded        (8.5 KB)
    __shared__ float Vsm[32*DK];      // V tile [kk][d]                (8 KB)
    __shared__ float Qs [32*DK];      // 32 q rows                     (8 KB)
    __shared__ float Csm[32*SS];      // cope logits per q row         (16 KB)
    __shared__ float Psm[16][32][2];  // [warp][kk][r] prob strip      (4 KB)

    const int tid  = threadIdx.x;
    const int w    = tid >> 5;
    const int lane = tid & 31;
    const int b    = blockIdx.y;
    const int q0   = (gridDim.x - 1 - blockIdx.x) * 32;   // heavy-first
    const int bL   = b * LL;
    const bool midq = (q0 >= MIDLO) && (q0 < MIDHI);   // uniform within CTA
    const int wq0l  = w * 2;             // first local q row of this warp
    const int wq0g  = q0 + wq0l;         // first global q row of this warp
    const int qg1   = wq0g + 1;          // last q row of this warp
    const int qmaxc = q0 + 31;           // last q row of CTA

    // Load Q tile (32x64 floats = 512 float4; one per thread)
    {
        const int row = tid >> 4, d4 = (tid & 15) << 2;
        *(float4*)&Qs[row*DK + d4] =
            *(const float4*)&g_Q[(size_t)(bL + q0 + row)*DK + d4];
    }
    __syncthreads();

    // CoPE logits for this warp's 2 rows: Csm[r][j] = q_r . cope[:, j]
    float c127[2] = {0.f,0.f};           // Csm[row][127], the saturated bias
    if (midq) {
        float4 ca[2] = {{0,0,0,0},{0,0,0,0}};
        const int j4 = lane * 4;
        #pragma unroll 4
        for (int d = 0; d < DK; d++) {
            const float4 cv = *(const float4*)&cope[d*SS + j4];
            #pragma unroll
            for (int r = 0; r < 2; r++) {
                const float qd = Qs[(wq0l + r)*DK + d];
                ca[r].x += qd*cv.x; ca[r].y += qd*cv.y;
                ca[r].z += qd*cv.z; ca[r].w += qd*cv.w;
            }
        }
        #pragma unroll
        for (int r = 0; r < 2; r++) {
            *(float4*)&Csm[(wq0l + r)*SS + j4] = ca[r];
            c127[r] = __shfl_sync(0xffffffffu, ca[r].w, 31);  // j=127 = lane31 .w
        }
    }

    float l[2]     = {0.f,0.f};          // per-lane partial softmax denom
    float carry[2] = {0.f,0.f};
    float acc[2][2] = {{0.f,0.f},{0.f,0.f}};

    const int kkl   = 31 - lane;         // tile-local k, descending across lanes
    const int t_cau = qmaxc >> 5;        // last tile index with any causal score
    int t = midq ? (MIDHI/32 - 1) : t_cau;

    // ================= Phase 1: gate region (mid CTAs only) =================
    if (midq) {
        for (; t >= 0; t--) {
            // Saturation vote doubles as the tile barrier.
            const bool wsat = (carry[0] >= 127.f) & (carry[1] >= 127.f);
            if (__syncthreads_and(wsat)) break;

            const int  kb       = t * 32;
            const bool tile_mid = (kb >= MIDLO);
            const bool ctascore = (kb <= qmaxc);

            {
                const int kk = tid >> 4, d4 = (tid & 15) << 2;
                *(float4*)&Ksm[kk*KROW + d4] =
                    *(const float4*)&g_K[(size_t)(bL + kb + kk)*DK + d4];
                if (ctascore)
                    *(float4*)&Vsm[kk*DK + d4] =
                        *(const float4*)&g_V[(size_t)(bL + kb + kk)*DK + d4];
            }
            __syncthreads();

            const bool need_gate = tile_mid;
            const bool anyw      = (kb <= qg1);

            if (need_gate || anyw) {
                float dot[2] = {0.f,0.f};
                {
                    const float4* kp = (const float4*)&Ksm[kkl*KROW];
                    #pragma unroll 8
                    for (int c = 0; c < 16; c++) {
                        const float4 kv = kp[c];
                        #pragma unroll
                        for (int r = 0; r < 2; r++) {
                            const float4 qv = *(const float4*)&Qs[(wq0l + r)*DK + c*4];
                            dot[r] += kv.x*qv.x + kv.y*qv.y + kv.z*qv.z + kv.w*qv.w;
                        }
                    }
                }

                float pos[2] = {0.f,0.f};
                if (need_gate) {
                    #pragma unroll
                    for (int r = 0; r < 2; r++) {
                        const float gg = 1.f / (1.f + __expf(-dot[r]));
                        float pref = gg;
                        #pragma unroll
                        for (int o = 1; o < 32; o <<= 1) {
                            const float nv = __shfl_up_sync(0xffffffffu, pref, o);
                            if (lane >= o) pref += nv;
                        }
                        pos[r] = carry[r] + pref;
                        carry[r] += __shfl_sync(0xffffffffu, pref, 31);
                    }
                }

                if (anyw) {
                    const int kglob = kb + kkl;
                    float p[2];
                    #pragma unroll
                    for (int r = 0; r < 2; r++) {
                        const int qr = wq0g + r;
                        float s = -1e30f;
                        if (kglob <= qr) {
                            s = dot[r] * SCALE;
                            if (need_gate) {
                                const float pc  = fminf(pos[r], (float)(SS-1));
                                const float pf  = floorf(pc);
                                const int   ic  = (int)ceilf(pc);
                                const int   ifl = (int)pf;
                                const float wf  = pc - pf;
                                const float* cr = &Csm[(wq0l + r)*SS];
                                s += cr[ic]*wf + cr[ifl]*(1.f - wf);
                            }
                        }
                        p[r] = __expf(s);
                        l[r] += p[r];
                    }

                    *(float2*)&Psm[w][kkl][0] = make_float2(p[0], p[1]);
                    __syncwarp();
                    const int d2 = 2*lane;
                    #pragma unroll 8
                    for (int kk = 0; kk < 32; kk++) {
                        const float2 pv = *(const float2*)&Psm[w][kk][0];
                        const float2 vv = *(const float2*)&Vsm[kk*DK + d2];
                        acc[0][0] += pv.x*vv.x; acc[0][1] += pv.x*vv.y;
                        acc[1][0] += pv.y*vv.x; acc[1][1] += pv.y*vv.y;
                    }
                    __syncwarp();
                }
            }
        }
    }

    // ============ Phase 2: causal-only tiles, saturated bias = c127 ==========
    for (int t2 = (t < t_cau ? t : t_cau); t2 >= 0; t2--) {
        const int  kb       = t2 * 32;
        const bool tile_mid = midq && (kb >= MIDLO);   // bias = exact 127-clamp

        __syncthreads();
        {
            const int kk = tid >> 4, d4 = (tid & 15) << 2;
            *(float4*)&Ksm[kk*KROW + d4] =
                *(const float4*)&g_K[(size_t)(bL + kb + kk)*DK + d4];
            *(float4*)&Vsm[kk*DK + d4] =
                *(const float4*)&g_V[(size_t)(bL + kb + kk)*DK + d4];
        }
        __syncthreads();

        if (kb <= qg1) {
            float dot[2] = {0.f,0.f};
            {
                const float4* kp = (const float4*)&Ksm[kkl*KROW];
                #pragma unroll 8
                for (int c = 0; c < 16; c++) {
                    const float4 kv = kp[c];
                    #pragma unroll
                    for (int r = 0; r < 2; r++) {
                        const float4 qv = *(const float4*)&Qs[(wq0l + r)*DK + c*4];
                        dot[r] += kv.x*qv.x + kv.y*qv.y + kv.z*qv.z + kv.w*qv.w;
                    }
                }
            }

            const int kglob = kb + kkl;
            float p[2];
            #pragma unroll
            for (int r = 0; r < 2; r++) {
                const int qr = wq0g + r;
                float s = -1e30f;
                if (kglob <= qr) {
                    s = dot[r] * SCALE;
                    if (tile_mid) s += c127[r];
                }
                p[r] = __expf(s);
                l[r] += p[r];
            }

            *(float2*)&Psm[w][kkl][0] = make_float2(p[0], p[1]);
            __syncwarp();
            const int d2 = 2*lane;
            #pragma unroll 8
            for (int kk = 0; kk < 32; kk++) {
                const float2 pv = *(const float2*)&Psm[w][kk][0];
                const float2 vv = *(const float2*)&Vsm[kk*DK + d2];
                acc[0][0] += pv.x*vv.x; acc[0][1] += pv.x*vv.y;
                acc[1][0] += pv.y*vv.x; acc[1][1] += pv.y*vv.y;
            }
            __syncwarp();
        }
    }

    // Final: reduce per-lane denominators once, normalize, store.
    #pragma unroll
    for (int r = 0; r < 2; r++) {
        float lr = l[r];
        #pragma unroll
        for (int o = 16; o; o >>= 1) lr += __shfl_xor_sync(0xffffffffu, lr, o);
        const float inv = 1.f / lr;
        float2 o2; o2.x = acc[r][0]*inv; o2.y = acc[r][1]*inv;
        *(float2*)&out[(size_t)(bL + wq0g + r)*DK + 2*lane] = o2;
    }
}

// ---------------------------------------------------------------------------
extern "C" void kernel_launch(void* const* d_in, const int* in_sizes, int n_in,
                              void* d_out, int out_size)
{
    const float* x    = (const float*)d_in[0];
    const float* Wq   = (const float*)d_in[1];
    const float* Wk   = (const float*)d_in[2];
    const float* Wv   = (const float*)d_in[3];
    const float* Wqs  = (const float*)d_in[4];
    const float* Wks  = (const float*)d_in[5];
    const float* Wvs  = (const float*)d_in[6];
    const float* Wqe  = (const float*)d_in[7];
    const float* Wke  = (const float*)d_in[8];
    const float* Wve  = (const float*)d_in[9];
    const float* lg   = (const float*)d_in[10];
    const float* lb   = (const float*)d_in[11];
    const float* lsg  = (const float*)d_in[12];
    const float* lsb  = (const float*)d_in[13];
    const float* leg  = (const float*)d_in[14];
    const float* leb  = (const float*)d_in[15];
    const float* cope = (const float*)d_in[16];
    float* out = (float*)d_out;

    ln_proj_kernel<<<NROW/RPC, 256>>>(x, Wq, Wk, Wv, Wqs, Wks, Wvs, Wqe, Wke, Wve,
                                      lg, lb, lsg, lsb, leg, leb);
    attn_kernel<<<dim3(LL/32, BB), 512>>>(cope, out);
}

// round 13
// speedup vs baseline: 1.4083x; 1.4083x over previous
#include <cuda_runtime.h>
#include <math.h>

// Problem constants
#define BB    4
#define SS    128
#define LL    2304          // SEQ + 2S
#define DIN   512
#define DK    64
#define NROW  (BB*LL)       // 9216
#define MIDLO SS            // 128
#define MIDHI (LL-SS)       // 2176
#define SCALE 0.125f        // 1/sqrt(64)

// Scratch: projected Q/K/V for all rows
__device__ float g_Q[NROW*DK];
__device__ float g_K[NROW*DK];
__device__ float g_V[NROW*DK];

// ---------------------------------------------------------------------------
// Kernel 1: LayerNorm + QKV projection. 16 rows per CTA, float4 xn reads.
// ---------------------------------------------------------------------------
#define RPC 16
__global__ __launch_bounds__(256) void ln_proj_kernel(
    const float* __restrict__ x,
    const float* __restrict__ Wq,  const float* __restrict__ Wk,  const float* __restrict__ Wv,
    const float* __restrict__ Wqs, const float* __restrict__ Wks, const float* __restrict__ Wvs,
    const float* __restrict__ Wqe, const float* __restrict__ Wke, const float* __restrict__ Wve,
    const float* __restrict__ lg,  const float* __restrict__ lb,
    const float* __restrict__ lsg, const float* __restrict__ lsb,
    const float* __restrict__ leg, const float* __restrict__ leb)
{
    __shared__ float xn[RPC*DIN];                // 32 KB normalized rows
    const int tid  = threadIdx.x;
    const int w    = tid >> 5;
    const int lane = tid & 31;
    const int r0   = blockIdx.x * RPC;           // segment bounds are %16 == 0
    const int rloc = r0 % LL;
    const int seg  = (rloc < SS) ? 1 : (rloc >= MIDHI ? 2 : 0);

    const float* g  = seg==0 ? lg : (seg==1 ? lsg : leg);
    const float* be = seg==0 ? lb : (seg==1 ? lsb : leb);

    #pragma unroll
    for (int rr = 0; rr < 2; rr++) {
        const int rl = w*2 + rr;
        const float* xr = x + (size_t)(r0 + rl) * DIN;
        float s = 0.f, s2 = 0.f;
        for (int i = lane; i < DIN; i += 32) { float v = xr[i]; s += v; s2 += v*v; }
        #pragma unroll
        for (int o = 16; o; o >>= 1) {
            s  += __shfl_xor_sync(0xffffffffu, s,  o);
            s2 += __shfl_xor_sync(0xffffffffu, s2, o);
        }
        const float mean = s * (1.0f/DIN);
        const float var  = s2 * (1.0f/DIN) - mean*mean;
        const float rstd = rsqrtf(var + 1e-5f);
        for (int i = lane; i < DIN; i += 32)
            xn[rl*DIN + i] = (xr[i] - mean) * rstd * g[i] + be[i];
    }
    __syncthreads();

    if (tid < 192) {
        const float* W; float* dst; int col;
        if (tid < 64)       { W = seg==0 ? Wq : (seg==1 ? Wqs : Wqe); dst = g_Q; col = tid; }
        else if (tid < 128) { W = seg==0 ? Wk : (seg==1 ? Wks : Wke); dst = g_K; col = tid - 64; }
        else                { W = seg==0 ? Wv : (seg==1 ? Wvs : Wve); dst = g_V; col = tid - 128; }

        float acc[RPC];
        #pragma unroll
        for (int r = 0; r < RPC; r++) acc[r] = 0.f;

        for (int i4 = 0; i4 < DIN/4; i4++) {
            const int i = i4 * 4;
            const float w0 = W[(i+0)*DK + col];
            const float w1 = W[(i+1)*DK + col];
            const float w2 = W[(i+2)*DK + col];
            const float w3 = W[(i+3)*DK + col];
            #pragma unroll
            for (int r = 0; r < RPC; r++) {
                const float4 x4 = *(const float4*)&xn[r*DIN + i];
                acc[r] += x4.x*w0 + x4.y*w1 + x4.z*w2 + x4.w*w3;
            }
        }
        #pragma unroll
        for (int r = 0; r < RPC; r++) dst[(size_t)(r0 + r)*DK + col] = acc[r];
    }
}

// ---------------------------------------------------------------------------
// Kernel 2: fused CoPE-gated causal attention.
//  - CTA: 32 q rows, 256 threads, 8 warps; warp = 4 q rows (R11 config).
//  - Phase 1 (mid CTAs): k-tiles of 32 DESCENDING with gate prefix scan,
//    until CTA-wide saturation vote (pos clamps to exactly 127 after the
//    suffix sum crosses 127 -> bias = c127 const).
//  - Phase 2: ASCENDING 64-key tiles (order-free), lean body, SMEM union
//    reuses the dead Csm region, software-pipelined global loads.
// ---------------------------------------------------------------------------
#define KROW 68
// SMEM union (bytes):
//  phase1: Csm @0 (16384) | K1 @16384 (8704) | V1 @25088 (8192) | P1 @33280 (4096)
//  phase2: K2  @0 (17408) | V2 @17408 (16384)                   | P2 @33792 (4096)
#define SMEMU_BYTES 37888
__global__ __launch_bounds__(256, 2) void attn_kernel(
    const float* __restrict__ cope,   // [64][128] row-major
    float* __restrict__ out)          // [B][L][64]
{
    __shared__ __align__(16) char smemu[SMEMU_BYTES];
    __shared__ float Qs[32*DK];       // 8 KB, persistent

    float* const Csm = (float*)(smemu);            // 32*128
    float* const K1  = (float*)(smemu + 16384);    // 32*KROW
    float* const V1  = (float*)(smemu + 25088);    // 32*64
    float* const P1  = (float*)(smemu + 33280);    // 8*32*4
    float* const K2  = (float*)(smemu);            // 64*KROW
    float* const V2  = (float*)(smemu + 17408);    // 64*64
    float* const P2  = (float*)(smemu + 33792);    // 8*32*4

    const int tid  = threadIdx.x;
    const int w    = tid >> 5;
    const int lane = tid & 31;
    const int b    = blockIdx.y;
    const int q0   = (gridDim.x - 1 - blockIdx.x) * 32;   // heavy-first
    const int bL   = b * LL;
    const bool midq = (q0 >= MIDLO) && (q0 < MIDHI);
    const int wq0l  = w * 4;
    const int wq0g  = q0 + wq0l;
    const int qg3   = wq0g + 3;
    const int qmaxc = q0 + 31;

    // Load Q tile (32x64 floats = 512 float4)
    for (int i = tid; i < 512; i += 256) {
        const int row = i >> 4, d4q = (i & 15) << 2;
        *(float4*)&Qs[row*DK + d4q] =
            *(const float4*)&g_Q[(size_t)(bL + q0 + row)*DK + d4q];
    }
    __syncthreads();

    // CoPE logits: Csm[r][j] = q_r . cope[:, j];  c127 = saturated bias
    float c127[4] = {0.f,0.f,0.f,0.f};
    if (midq) {
        float4 ca[4] = {{0,0,0,0},{0,0,0,0},{0,0,0,0},{0,0,0,0}};
        const int j4 = lane * 4;
        #pragma unroll 4
        for (int d = 0; d < DK; d++) {
            const float4 cv = *(const float4*)&cope[d*SS + j4];
            #pragma unroll
            for (int r = 0; r < 4; r++) {
                const float qd = Qs[(wq0l + r)*DK + d];
                ca[r].x += qd*cv.x; ca[r].y += qd*cv.y;
                ca[r].z += qd*cv.z; ca[r].w += qd*cv.w;
            }
        }
        #pragma unroll
        for (int r = 0; r < 4; r++) {
            *(float4*)&Csm[(wq0l + r)*SS + j4] = ca[r];
            c127[r] = __shfl_sync(0xffffffffu, ca[r].w, 31);  // j=127 = lane31 .w
        }
    }

    float l[4]     = {0.f,0.f,0.f,0.f};
    float carry[4] = {0.f,0.f,0.f,0.f};
    float acc[4][2] = {{0.f,0.f},{0.f,0.f},{0.f,0.f},{0.f,0.f}};

    const int kkl   = 31 - lane;         // tile-local k, descending across lanes
    const int t_cau = qmaxc >> 5;
    int t = midq ? (MIDHI/32 - 1) : t_cau;

    // ================= Phase 1: gate region (mid CTAs, 32-k tiles) ==========
    if (midq) {
        for (; t >= 0; t--) {
            const bool wsat = (carry[0] >= 127.f) & (carry[1] >= 127.f) &
                              (carry[2] >= 127.f) & (carry[3] >= 127.f);
            if (__syncthreads_and(wsat)) break;   // also fences SMEM reuse

            const int  kb       = t * 32;
            const bool tile_mid = (kb >= MIDLO);
            const bool ctascore = (kb <= qmaxc);

            for (int i = tid; i < 512; i += 256) {
                const int kk = i >> 4, d4q = (i & 15) << 2;
                *(float4*)&K1[kk*KROW + d4q] =
                    *(const float4*)&g_K[(size_t)(bL + kb + kk)*DK + d4q];
                if (ctascore)
                    *(float4*)&V1[kk*DK + d4q] =
                        *(const float4*)&g_V[(size_t)(bL + kb + kk)*DK + d4q];
            }
            __syncthreads();

            const bool anyw = (kb <= qg3);

            float dot[4] = {0.f,0.f,0.f,0.f};
            {
                const float4* kp = (const float4*)&K1[kkl*KROW];
                #pragma unroll 8
                for (int c = 0; c < 16; c++) {
                    const float4 kv = kp[c];
                    #pragma unroll
                    for (int r = 0; r < 4; r++) {
                        const float4 qv = *(const float4*)&Qs[(wq0l + r)*DK + c*4];
                        dot[r] += kv.x*qv.x + kv.y*qv.y + kv.z*qv.z + kv.w*qv.w;
                    }
                }
            }

            float pos[4] = {0.f,0.f,0.f,0.f};
            if (tile_mid) {
                #pragma unroll
                for (int r = 0; r < 4; r++) {
                    const float gg = 1.f / (1.f + __expf(-dot[r]));
                    float pref = gg;
                    #pragma unroll
                    for (int o = 1; o < 32; o <<= 1) {
                        const float nv = __shfl_up_sync(0xffffffffu, pref, o);
                        if (lane >= o) pref += nv;
                    }
                    pos[r] = carry[r] + pref;
                    carry[r] += __shfl_sync(0xffffffffu, pref, 31);
                }
            }

            if (anyw) {
                const int kglob = kb + kkl;
                float p[4];
                #pragma unroll
                for (int r = 0; r < 4; r++) {
                    const int qr = wq0g + r;
                    float s = -1e30f;
                    if (kglob <= qr) {
                        s = dot[r] * SCALE;
                        if (tile_mid) {
                            const float pc  = fminf(pos[r], (float)(SS-1));
                            const float pf  = floorf(pc);
                            const int   ic  = (int)ceilf(pc);
                            const int   ifl = (int)pf;
                            const float wf  = pc - pf;
                            const float* cr = &Csm[(wq0l + r)*SS];
                            s += cr[ic]*wf + cr[ifl]*(1.f - wf);
                        }
                    }
                    p[r] = __expf(s);
                    l[r] += p[r];
                }

                *(float4*)&P1[(w*32 + kkl)*4] = make_float4(p[0], p[1], p[2], p[3]);
                __syncwarp();
                const int d2 = 2*lane;
                #pragma unroll 8
                for (int kk = 0; kk < 32; kk++) {
                    const float4 pv = *(const float4*)&P1[(w*32 + kk)*4];
                    const float2 vv = *(const float2*)&V1[kk*DK + d2];
                    acc[0][0] += pv.x*vv.x; acc[0][1] += pv.x*vv.y;
                    acc[1][0] += pv.y*vv.x; acc[1][1] += pv.y*vv.y;
                    acc[2][0] += pv.z*vv.x; acc[2][1] += pv.z*vv.y;
                    acc[3][0] += pv.w*vv.x; acc[3][1] += pv.w*vv.y;
                }
                __syncwarp();
            }
        }
    }

    // ===== Phase 2: ascending 64-key tiles, bias = c127, pipelined loads =====
    {
        const int hi  = (t < t_cau ? t : t_cau);
        const int n_k = (hi + 1) * 32;            // keys still to process (0 if none)
        const int ld_row0 = tid >> 4;             // 0..15
        const int ld_d4   = (tid & 15) << 2;

        float4 kf[4], vf[4];
        // prefetch block 0
        if (n_k > 0) {
            #pragma unroll
            for (int j = 0; j < 4; j++) {
                const int row = ld_row0 + j*16;
                if (row < n_k) {
                    kf[j] = *(const float4*)&g_K[(size_t)(bL + row)*DK + ld_d4];
                    vf[j] = *(const float4*)&g_V[(size_t)(bL + row)*DK + ld_d4];
                }
            }
        }

        for (int kb = 0; kb < n_k; kb += 64) {
            __syncthreads();                      // fence prior SMEM readers
            #pragma unroll
            for (int j = 0; j < 4; j++) {
                const int row = ld_row0 + j*16;
                if (kb + row < n_k) {
                    *(float4*)&K2[row*KROW + ld_d4] = kf[j];
                    *(float4*)&V2[row*DK   + ld_d4] = vf[j];
                }
            }
            // prefetch next block (overlaps this tile's compute)
            if (kb + 64 < n_k) {
                #pragma unroll
                for (int j = 0; j < 4; j++) {
                    const int row = ld_row0 + j*16;
                    if (kb + 64 + row < n_k) {
                        kf[j] = *(const float4*)&g_K[(size_t)(bL + kb + 64 + row)*DK + ld_d4];
                        vf[j] = *(const float4*)&g_V[(size_t)(bL + kb + 64 + row)*DK + ld_d4];
                    }
                }
            }
            __syncthreads();

            if (kb <= qg3) {
                const bool biasOn = midq && (kb >= MIDLO);   // 64-blocks never straddle 128
                float dot[4]  = {0.f,0.f,0.f,0.f};
                float dot2[4] = {0.f,0.f,0.f,0.f};
                {
                    const float4* kp  = (const float4*)&K2[kkl*KROW];
                    const float4* kp2 = (const float4*)&K2[(kkl+32)*KROW];
                    #pragma unroll 8
                    for (int c = 0; c < 16; c++) {
                        const float4 kv  = kp[c];
                        const float4 kv2 = kp2[c];
                        #pragma unroll
                        for (int r = 0; r < 4; r++) {
                            const float4 qv = *(const float4*)&Qs[(wq0l + r)*DK + c*4];
                            dot[r]  += kv.x*qv.x  + kv.y*qv.y  + kv.z*qv.z  + kv.w*qv.w;
                            dot2[r] += kv2.x*qv.x + kv2.y*qv.y + kv2.z*qv.z + kv2.w*qv.w;
                        }
                    }
                }

                const int kglob  = kb + kkl;
                const int kglob2 = kglob + 32;
                float p[4], p2[4];
                #pragma unroll
                for (int r = 0; r < 4; r++) {
                    const int qr = wq0g + r;
                    float s = -1e30f, s2 = -1e30f;
                    if (kglob <= qr) {
                        s = dot[r] * SCALE;
                        if (biasOn) s += c127[r];
                    }
                    if (kglob2 <= qr && kglob2 < n_k) {
                        s2 = dot2[r] * SCALE;
                        if (biasOn) s2 += c127[r];
                    }
                    p[r]  = __expf(s);
                    p2[r] = __expf(s2);
                    l[r] += p[r] + p2[r];
                }

                const int d2 = 2*lane;
                // PV half 0 (keys kb..kb+31)
                *(float4*)&P2[(w*32 + kkl)*4] = make_float4(p[0], p[1], p[2], p[3]);
                __syncwarp();
                #pragma unroll 8
                for (int kk = 0; kk < 32; kk++) {
                    const float4 pv = *(const float4*)&P2[(w*32 + kk)*4];
                    const float2 vv = *(const float2*)&V2[kk*DK + d2];
                    acc[0][0] += pv.x*vv.x; acc[0][1] += pv.x*vv.y;
                    acc[1][0] += pv.y*vv.x; acc[1][1] += pv.y*vv.y;
                    acc[2][0] += pv.z*vv.x; acc[2][1] += pv.z*vv.y;
                    acc[3][0] += pv.w*vv.x; acc[3][1] += pv.w*vv.y;
                }
                __syncwarp();
                // PV half 1 (keys kb+32..kb+63), skip if fully masked/absent
                if (kb + 32 <= qg3 && kb + 32 < n_k) {
                    *(float4*)&P2[(w*32 + kkl)*4] = make_float4(p2[0], p2[1], p2[2], p2[3]);
                    __syncwarp();
                    #pragma unroll 8
                    for (int kk = 0; kk < 32; kk++) {
                        const float4 pv = *(const float4*)&P2[(w*32 + kk)*4];
                        const float2 vv = *(const float2*)&V2[(kk+32)*DK + d2];
                        acc[0][0] += pv.x*vv.x; acc[0][1] += pv.x*vv.y;
                        acc[1][0] += pv.y*vv.x; acc[1][1] += pv.y*vv.y;
                        acc[2][0] += pv.z*vv.x; acc[2][1] += pv.z*vv.y;
                        acc[3][0] += pv.w*vv.x; acc[3][1] += pv.w*vv.y;
                    }
                    __syncwarp();
                }
            }
        }
    }

    // Final: reduce per-lane denominators once, normalize, store.
    #pragma unroll
    for (int r = 0; r < 4; r++) {
        float lr = l[r];
        #pragma unroll
        for (int o = 16; o; o >>= 1) lr += __shfl_xor_sync(0xffffffffu, lr, o);
        const float inv = 1.f / lr;
        float2 o2; o2.x = acc[r][0]*inv; o2.y = acc[r][1]*inv;
        *(float2*)&out[(size_t)(bL + wq0g + r)*DK + 2*lane] = o2;
    }
}

// ---------------------------------------------------------------------------
extern "C" void kernel_launch(void* const* d_in, const int* in_sizes, int n_in,
                              void* d_out, int out_size)
{
    const float* x    = (const float*)d_in[0];
    const float* Wq   = (const float*)d_in[1];
    const float* Wk   = (const float*)d_in[2];
    const float* Wv   = (const float*)d_in[3];
    const float* Wqs  = (const float*)d_in[4];
    const float* Wks  = (const float*)d_in[5];
    const float* Wvs  = (const float*)d_in[6];
    const float* Wqe  = (const float*)d_in[7];
    const float* Wke  = (const float*)d_in[8];
    const float* Wve  = (const float*)d_in[9];
    const float* lg   = (const float*)d_in[10];
    const float* lb   = (const float*)d_in[11];
    const float* lsg  = (const float*)d_in[12];
    const float* lsb  = (const float*)d_in[13];
    const float* leg  = (const float*)d_in[14];
    const float* leb  = (const float*)d_in[15];
    const float* cope = (const float*)d_in[16];
    float* out = (float*)d_out;

    ln_proj_kernel<<<NROW/RPC, 256>>>(x, Wq, Wk, Wv, Wqs, Wks, Wvs, Wqe, Wke, Wve,
                                      lg, lb, lsg, lsb, leg, leb);
    attn_kernel<<<dim3(LL/32, BB), 256>>>(cope, out);
}

// round 14
// speedup vs baseline: 1.4256x; 1.0123x over previous
#include <cuda_runtime.h>
#include <math.h>

// Problem constants
#define BB    4
#define SS    128
#define LL    2304          // SEQ + 2S
#define DIN   512
#define DK    64
#define NROW  (BB*LL)       // 9216
#define MIDLO SS            // 128
#define MIDHI (LL-SS)       // 2176
#define SCALE 0.125f        // 1/sqrt(64)

// Scratch: projected Q/K/V for all rows
__device__ float g_Q[NROW*DK];
__device__ float g_K[NROW*DK];
__device__ float g_V[NROW*DK];

// ---------------------------------------------------------------------------
// Kernel 1: LayerNorm + QKV projection. 16 rows per CTA, float4 xn reads.
// ---------------------------------------------------------------------------
#define RPC 16
__global__ __launch_bounds__(256) void ln_proj_kernel(
    const float* __restrict__ x,
    const float* __restrict__ Wq,  const float* __restrict__ Wk,  const float* __restrict__ Wv,
    const float* __restrict__ Wqs, const float* __restrict__ Wks, const float* __restrict__ Wvs,
    const float* __restrict__ Wqe, const float* __restrict__ Wke, const float* __restrict__ Wve,
    const float* __restrict__ lg,  const float* __restrict__ lb,
    const float* __restrict__ lsg, const float* __restrict__ lsb,
    const float* __restrict__ leg, const float* __restrict__ leb)
{
    __shared__ float xn[RPC*DIN];                // 32 KB normalized rows
    const int tid  = threadIdx.x;
    const int w    = tid >> 5;
    const int lane = tid & 31;
    const int r0   = blockIdx.x * RPC;           // segment bounds are %16 == 0
    const int rloc = r0 % LL;
    const int seg  = (rloc < SS) ? 1 : (rloc >= MIDHI ? 2 : 0);

    const float* g  = seg==0 ? lg : (seg==1 ? lsg : leg);
    const float* be = seg==0 ? lb : (seg==1 ? lsb : leb);

    #pragma unroll
    for (int rr = 0; rr < 2; rr++) {
        const int rl = w*2 + rr;
        const float* xr = x + (size_t)(r0 + rl) * DIN;
        float s = 0.f, s2 = 0.f;
        for (int i = lane; i < DIN; i += 32) { float v = xr[i]; s += v; s2 += v*v; }
        #pragma unroll
        for (int o = 16; o; o >>= 1) {
            s  += __shfl_xor_sync(0xffffffffu, s,  o);
            s2 += __shfl_xor_sync(0xffffffffu, s2, o);
        }
        const float mean = s * (1.0f/DIN);
        const float var  = s2 * (1.0f/DIN) - mean*mean;
        const float rstd = rsqrtf(var + 1e-5f);
        for (int i = lane; i < DIN; i += 32)
            xn[rl*DIN + i] = (xr[i] - mean) * rstd * g[i] + be[i];
    }
    __syncthreads();

    if (tid < 192) {
        const float* W; float* dst; int col;
        if (tid < 64)       { W = seg==0 ? Wq : (seg==1 ? Wqs : Wqe); dst = g_Q; col = tid; }
        else if (tid < 128) { W = seg==0 ? Wk : (seg==1 ? Wks : Wke); dst = g_K; col = tid - 64; }
        else                { W = seg==0 ? Wv : (seg==1 ? Wvs : Wve); dst = g_V; col = tid - 128; }

        float acc[RPC];
        #pragma unroll
        for (int r = 0; r < RPC; r++) acc[r] = 0.f;

        for (int i4 = 0; i4 < DIN/4; i4++) {
            const int i = i4 * 4;
            const float w0 = W[(i+0)*DK + col];
            const float w1 = W[(i+1)*DK + col];
            const float w2 = W[(i+2)*DK + col];
            const float w3 = W[(i+3)*DK + col];
            #pragma unroll
            for (int r = 0; r < RPC; r++) {
                const float4 x4 = *(const float4*)&xn[r*DIN + i];
                acc[r] += x4.x*w0 + x4.y*w1 + x4.z*w2 + x4.w*w3;
            }
        }
        #pragma unroll
        for (int r = 0; r < RPC; r++) dst[(size_t)(r0 + r)*DK + col] = acc[r];
    }
}

// ---------------------------------------------------------------------------
// Kernel 2: fused CoPE-gated causal attention.
//  - CTA: 32 q rows, 256 threads, 8 warps; warp = 4 q rows.
//  - Phase 1 (mid CTAs): 32-k tiles DESCENDING with gate suffix-sum, now with
//    register-prefetch pipelining and a cheap butterfly-sum path for tiles
//    where this warp has no causal scores (pos unused -> only carry needed).
//    Runs until CTA-wide saturation vote (pos clamps to exactly 127).
//  - Phase 2: ASCENDING 64-key tiles, lean body (bias = c127 const),
//    SMEM union over the dead Csm region, register-prefetch pipelining.
// ---------------------------------------------------------------------------
#define KROW 68
// SMEM union (bytes):
//  phase1: Csm @0 (16384) | K1 @16384 (8704) | V1 @25088 (8192) | P1 @33280 (4096)
//  phase2: K2  @0 (17408) | V2 @17408 (16384)                   | P2 @33792 (4096)
#define SMEMU_BYTES 37888
__global__ __launch_bounds__(256, 2) void attn_kernel(
    const float* __restrict__ cope,   // [64][128] row-major
    float* __restrict__ out)          // [B][L][64]
{
    __shared__ __align__(16) char smemu[SMEMU_BYTES];
    __shared__ float Qs[32*DK];       // 8 KB, persistent

    float* const Csm = (float*)(smemu);            // 32*128
    float* const K1  = (float*)(smemu + 16384);    // 32*KROW
    float* const V1  = (float*)(smemu + 25088);    // 32*64
    float* const P1  = (float*)(smemu + 33280);    // 8*32*4
    float* const K2  = (float*)(smemu);            // 64*KROW
    float* const V2  = (float*)(smemu + 17408);    // 64*64
    float* const P2  = (float*)(smemu + 33792);    // 8*32*4

    const int tid  = threadIdx.x;
    const int w    = tid >> 5;
    const int lane = tid & 31;
    const int b    = blockIdx.y;
    const int q0   = (gridDim.x - 1 - blockIdx.x) * 32;   // heavy-first
    const int bL   = b * LL;
    const bool midq = (q0 >= MIDLO) && (q0 < MIDHI);
    const int wq0l  = w * 4;
    const int wq0g  = q0 + wq0l;
    const int qg3   = wq0g + 3;
    const int qmaxc = q0 + 31;

    // Load Q tile (32x64 floats = 512 float4)
    for (int i = tid; i < 512; i += 256) {
        const int row = i >> 4, d4q = (i & 15) << 2;
        *(float4*)&Qs[row*DK + d4q] =
            *(const float4*)&g_Q[(size_t)(bL + q0 + row)*DK + d4q];
    }
    __syncthreads();

    // CoPE logits: Csm[r][j] = q_r . cope[:, j];  c127 = saturated bias
    float c127[4] = {0.f,0.f,0.f,0.f};
    if (midq) {
        float4 ca[4] = {{0,0,0,0},{0,0,0,0},{0,0,0,0},{0,0,0,0}};
        const int j4 = lane * 4;
        #pragma unroll 4
        for (int d = 0; d < DK; d++) {
            const float4 cv = *(const float4*)&cope[d*SS + j4];
            #pragma unroll
            for (int r = 0; r < 4; r++) {
                const float qd = Qs[(wq0l + r)*DK + d];
                ca[r].x += qd*cv.x; ca[r].y += qd*cv.y;
                ca[r].z += qd*cv.z; ca[r].w += qd*cv.w;
            }
        }
        #pragma unroll
        for (int r = 0; r < 4; r++) {
            *(float4*)&Csm[(wq0l + r)*SS + j4] = ca[r];
            c127[r] = __shfl_sync(0xffffffffu, ca[r].w, 31);  // j=127 = lane31 .w
        }
    }

    float l[4]     = {0.f,0.f,0.f,0.f};
    float carry[4] = {0.f,0.f,0.f,0.f};
    float acc[4][2] = {{0.f,0.f},{0.f,0.f},{0.f,0.f},{0.f,0.f}};

    const int kkl   = 31 - lane;         // tile-local k, descending across lanes
    const int t_cau = qmaxc >> 5;
    int t = midq ? (MIDHI/32 - 1) : t_cau;

    // ===== Phase 1: gate region (mid CTAs, 32-k tiles, prefetch pipeline) ====
    if (midq) {
        const int ld_row = tid >> 4;           // 0..15 -> rows ld_row, ld_row+16
        const int ld_d4  = (tid & 15) << 2;
        float4 kpf[2], vpf[2];
        bool pf_v = false;
        if (t >= 0) {                          // prefetch first tile
            const int kb = t * 32;
            pf_v = (kb <= qmaxc);
            #pragma unroll
            for (int j = 0; j < 2; j++) {
                const int row = ld_row + j*16;
                kpf[j] = *(const float4*)&g_K[(size_t)(bL + kb + row)*DK + ld_d4];
                if (pf_v)
                    vpf[j] = *(const float4*)&g_V[(size_t)(bL + kb + row)*DK + ld_d4];
            }
        }

        for (; t >= 0; t--) {
            const bool wsat = (carry[0] >= 127.f) & (carry[1] >= 127.f) &
                              (carry[2] >= 127.f) & (carry[3] >= 127.f);
            if (__syncthreads_and(wsat)) break;   // vote doubles as SMEM fence

            const int  kb       = t * 32;
            const bool tile_mid = (kb >= MIDLO);

            // store prefetched tile t
            #pragma unroll
            for (int j = 0; j < 2; j++) {
                const int row = ld_row + j*16;
                *(float4*)&K1[row*KROW + ld_d4] = kpf[j];
                if (pf_v) *(float4*)&V1[row*DK + ld_d4] = vpf[j];
            }
            // prefetch tile t-1 (overlaps this tile's compute)
            if (t - 1 >= 0) {
                const int kbn = kb - 32;
                pf_v = (kbn <= qmaxc);
                #pragma unroll
                for (int j = 0; j < 2; j++) {
                    const int row = ld_row + j*16;
                    kpf[j] = *(const float4*)&g_K[(size_t)(bL + kbn + row)*DK + ld_d4];
                    if (pf_v)
                        vpf[j] = *(const float4*)&g_V[(size_t)(bL + kbn + row)*DK + ld_d4];
                }
            }
            __syncthreads();

            const bool anyw = (kb <= qg3);

            float dot[4] = {0.f,0.f,0.f,0.f};
            {
                const float4* kp = (const float4*)&K1[kkl*KROW];
                #pragma unroll 8
                for (int c = 0; c < 16; c++) {
                    const float4 kv = kp[c];
                    #pragma unroll
                    for (int r = 0; r < 4; r++) {
                        const float4 qv = *(const float4*)&Qs[(wq0l + r)*DK + c*4];
                        dot[r] += kv.x*qv.x + kv.y*qv.y + kv.z*qv.z + kv.w*qv.w;
                    }
                }
            }

            if (anyw) {
                // full prefix scan (pos consumed by bias interpolation)
                float pos[4] = {0.f,0.f,0.f,0.f};
                if (tile_mid) {
                    #pragma unroll
                    for (int r = 0; r < 4; r++) {
                        const float gg = __fdividef(1.f, 1.f + __expf(-dot[r]));
                        float pref = gg;
                        #pragma unroll
                        for (int o = 1; o < 32; o <<= 1) {
                            const float nv = __shfl_up_sync(0xffffffffu, pref, o);
                            if (lane >= o) pref += nv;
                        }
                        pos[r] = carry[r] + pref;
                        carry[r] += __shfl_sync(0xffffffffu, pref, 31);
                    }
                }

                const int kglob = kb + kkl;
                float p[4];
                #pragma unroll
                for (int r = 0; r < 4; r++) {
                    const int qr = wq0g + r;
                    float s = -1e30f;
                    if (kglob <= qr) {
                        s = dot[r] * SCALE;
                        if (tile_mid) {
                            const float pc  = fminf(pos[r], (float)(SS-1));
                            const float pf  = floorf(pc);
                            const int   ic  = (int)ceilf(pc);
                            const int   ifl = (int)pf;
                            const float wf  = pc - pf;
                            const float* cr = &Csm[(wq0l + r)*SS];
                            s += cr[ic]*wf + cr[ifl]*(1.f - wf);
                        }
                    }
                    p[r] = __expf(s);
                    l[r] += p[r];
                }

                *(float4*)&P1[(w*32 + kkl)*4] = make_float4(p[0], p[1], p[2], p[3]);
                __syncwarp();
                const int d2 = 2*lane;
                #pragma unroll 8
                for (int kk = 0; kk < 32; kk++) {
                    const float4 pv = *(const float4*)&P1[(w*32 + kk)*4];
                    const float2 vv = *(const float2*)&V1[kk*DK + d2];
                    acc[0][0] += pv.x*vv.x; acc[0][1] += pv.x*vv.y;
                    acc[1][0] += pv.y*vv.x; acc[1][1] += pv.y*vv.y;
                    acc[2][0] += pv.z*vv.x; acc[2][1] += pv.z*vv.y;
                    acc[3][0] += pv.w*vv.x; acc[3][1] += pv.w*vv.y;
                }
                __syncwarp();
            } else if (tile_mid) {
                // gate-only: pos never consumed -> tile SUM suffices for carry
                #pragma unroll
                for (int r = 0; r < 4; r++) {
                    float gg = __fdividef(1.f, 1.f + __expf(-dot[r]));
                    #pragma unroll
                    for (int o = 16; o; o >>= 1)
                        gg += __shfl_xor_sync(0xffffffffu, gg, o);
                    carry[r] += gg;
                }
            }
        }
    }

    // ===== Phase 2: ascending 64-key tiles, bias = c127, pipelined loads =====
    {
        const int hi  = (t < t_cau ? t : t_cau);
        const int n_k = (hi + 1) * 32;            // keys still to process (0 if none)
        const int ld_row0 = tid >> 4;             // 0..15
        const int ld_d4   = (tid & 15) << 2;

        float4 kf[4], vf[4];
        if (n_k > 0) {                            // prefetch block 0
            #pragma unroll
            for (int j = 0; j < 4; j++) {
                const int row = ld_row0 + j*16;
                if (row < n_k) {
                    kf[j] = *(const float4*)&g_K[(size_t)(bL + row)*DK + ld_d4];
                    vf[j] = *(const float4*)&g_V[(size_t)(bL + row)*DK + ld_d4];
                }
            }
        }

        for (int kb = 0; kb < n_k; kb += 64) {
            __syncthreads();                      // fence prior SMEM readers
            #pragma unroll
            for (int j = 0; j < 4; j++) {
                const int row = ld_row0 + j*16;
                if (kb + row < n_k) {
                    *(float4*)&K2[row*KROW + ld_d4] = kf[j];
                    *(float4*)&V2[row*DK   + ld_d4] = vf[j];
                }
            }
            if (kb + 64 < n_k) {                  // prefetch next block
                #pragma unroll
                for (int j = 0; j < 4; j++) {
                    const int row = ld_row0 + j*16;
                    if (kb + 64 + row < n_k) {
                        kf[j] = *(const float4*)&g_K[(size_t)(bL + kb + 64 + row)*DK + ld_d4];
                        vf[j] = *(const float4*)&g_V[(size_t)(bL + kb + 64 + row)*DK + ld_d4];
                    }
                }
            }
            __syncthreads();

            if (kb <= qg3) {
                const bool biasOn = midq && (kb >= MIDLO);   // 64-blocks never straddle 128
                float dot[4]  = {0.f,0.f,0.f,0.f};
                float dot2[4] = {0.f,0.f,0.f,0.f};
                {
                    const float4* kp  = (const float4*)&K2[kkl*KROW];
                    const float4* kp2 = (const float4*)&K2[(kkl+32)*KROW];
                    #pragma unroll 8
                    for (int c = 0; c < 16; c++) {
                        const float4 kv  = kp[c];
                        const float4 kv2 = kp2[c];
                        #pragma unroll
                        for (int r = 0; r < 4; r++) {
                            const float4 qv = *(const float4*)&Qs[(wq0l + r)*DK + c*4];
                            dot[r]  += kv.x*qv.x  + kv.y*qv.y  + kv.z*qv.z  + kv.w*qv.w;
                            dot2[r] += kv2.x*qv.x + kv2.y*qv.y + kv2.z*qv.z + kv2.w*qv.w;
                        }
                    }
                }

                const int kglob  = kb + kkl;
                const int kglob2 = kglob + 32;
                float p[4], p2[4];
                #pragma unroll
                for (int r = 0; r < 4; r++) {
                    const int qr = wq0g + r;
                    float s = -1e30f, s2 = -1e30f;
                    if (kglob <= qr) {
                        s = dot[r] * SCALE;
                        if (biasOn) s += c127[r];
                    }
                    if (kglob2 <= qr && kglob2 < n_k) {
                        s2 = dot2[r] * SCALE;
                        if (biasOn) s2 += c127[r];
                    }
                    p[r]  = __expf(s);
                    p2[r] = __expf(s2);
                    l[r] += p[r] + p2[r];
                }

                const int d2 = 2*lane;
                *(float4*)&P2[(w*32 + kkl)*4] = make_float4(p[0], p[1], p[2], p[3]);
                __syncwarp();
                #pragma unroll 8
                for (int kk = 0; kk < 32; kk++) {
                    const float4 pv = *(const float4*)&P2[(w*32 + kk)*4];
                    const float2 vv = *(const float2*)&V2[kk*DK + d2];
                    acc[0][0] += pv.x*vv.x; acc[0][1] += pv.x*vv.y;
                    acc[1][0] += pv.y*vv.x; acc[1][1] += pv.y*vv.y;
                    acc[2][0] += pv.z*vv.x; acc[2][1] += pv.z*vv.y;
                    acc[3][0] += pv.w*vv.x; acc[3][1] += pv.w*vv.y;
                }
                __syncwarp();
                if (kb + 32 <= qg3 && kb + 32 < n_k) {
                    *(float4*)&P2[(w*32 + kkl)*4] = make_float4(p2[0], p2[1], p2[2], p2[3]);
                    __syncwarp();
                    #pragma unroll 8
                    for (int kk = 0; kk < 32; kk++) {
                        const float4 pv = *(const float4*)&P2[(w*32 + kk)*4];
                        const float2 vv = *(const float2*)&V2[(kk+32)*DK + d2];
                        acc[0][0] += pv.x*vv.x; acc[0][1] += pv.x*vv.y;
                        acc[1][0] += pv.y*vv.x; acc[1][1] += pv.y*vv.y;
                        acc[2][0] += pv.z*vv.x; acc[2][1] += pv.z*vv.y;
                        acc[3][0] += pv.w*vv.x; acc[3][1] += pv.w*vv.y;
                    }
                    __syncwarp();
                }
            }
        }
    }

    // Final: reduce per-lane denominators once, normalize, store.
    #pragma unroll
    for (int r = 0; r < 4; r++) {
        float lr = l[r];
        #pragma unroll
        for (int o = 16; o; o >>= 1) lr += __shfl_xor_sync(0xffffffffu, lr, o);
        const float inv = 1.f / lr;
        float2 o2; o2.x = acc[r][0]*inv; o2.y = acc[r][1]*inv;
        *(float2*)&out[(size_t)(bL + wq0g + r)*DK + 2*lane] = o2;
    }
}

// ---------------------------------------------------------------------------
extern "C" void kernel_launch(void* const* d_in, const int* in_sizes, int n_in,
                              void* d_out, int out_size)
{
    const float* x    = (const float*)d_in[0];
    const float* Wq   = (const float*)d_in[1];
    const float* Wk   = (const float*)d_in[2];
    const float* Wv   = (const float*)d_in[3];
    const float* Wqs  = (const float*)d_in[4];
    const float* Wks  = (const float*)d_in[5];
    const float* Wvs  = (const float*)d_in[6];
    const float* Wqe  = (const float*)d_in[7];
    const float* Wke  = (const float*)d_in[8];
    const float* Wve  = (const float*)d_in[9];
    const float* lg   = (const float*)d_in[10];
    const float* lb   = (const float*)d_in[11];
    const float* lsg  = (const float*)d_in[12];
    const float* lsb  = (const float*)d_in[13];
    const float* leg  = (const float*)d_in[14];
    const float* leb  = (const float*)d_in[15];
    const float* cope = (const float*)d_in[16];
    float* out = (float*)d_out;

    ln_proj_kernel<<<NROW/RPC, 256>>>(x, Wq, Wk, Wv, Wqs, Wks, Wvs, Wqe, Wke, Wve,
                                      lg, lb, lsg, lsb, leg, leb);
    attn_kernel<<<dim3(LL/32, BB), 256>>>(cope, out);
}

// round 15
// speedup vs baseline: 1.4806x; 1.0386x over previous
#include <cuda_runtime.h>
#include <math.h>

// Problem constants
#define BB    4
#define SS    128
#define LL    2304          // SEQ + 2S
#define DIN   512
#define DK    64
#define NROW  (BB*LL)       // 9216
#define MIDLO SS            // 128
#define MIDHI (LL-SS)       // 2176
#define SCALE 0.125f        // 1/sqrt(64)

// Scratch: projected Q/K/V for all rows
__device__ float g_Q[NROW*DK];
__device__ float g_K[NROW*DK];
__device__ float g_V[NROW*DK];

// ---------------------------------------------------------------------------
// Kernel 1: LayerNorm + QKV projection. 16 rows per CTA, float4 xn reads.
// ---------------------------------------------------------------------------
#define RPC 16
__global__ __launch_bounds__(256) void ln_proj_kernel(
    const float* __restrict__ x,
    const float* __restrict__ Wq,  const float* __restrict__ Wk,  const float* __restrict__ Wv,
    const float* __restrict__ Wqs, const float* __restrict__ Wks, const float* __restrict__ Wvs,
    const float* __restrict__ Wqe, const float* __restrict__ Wke, const float* __restrict__ Wve,
    const float* __restrict__ lg,  const float* __restrict__ lb,
    const float* __restrict__ lsg, const float* __restrict__ lsb,
    const float* __restrict__ leg, const float* __restrict__ leb)
{
    __shared__ float xn[RPC*DIN];                // 32 KB normalized rows
    const int tid  = threadIdx.x;
    const int w    = tid >> 5;
    const int lane = tid & 31;
    const int r0   = blockIdx.x * RPC;
    const int rloc = r0 % LL;
    const int seg  = (rloc < SS) ? 1 : (rloc >= MIDHI ? 2 : 0);

    const float* g  = seg==0 ? lg : (seg==1 ? lsg : leg);
    const float* be = seg==0 ? lb : (seg==1 ? lsb : leb);

    #pragma unroll
    for (int rr = 0; rr < 2; rr++) {
        const int rl = w*2 + rr;
        const float* xr = x + (size_t)(r0 + rl) * DIN;
        float s = 0.f, s2 = 0.f;
        for (int i = lane; i < DIN; i += 32) { float v = xr[i]; s += v; s2 += v*v; }
        #pragma unroll
        for (int o = 16; o; o >>= 1) {
            s  += __shfl_xor_sync(0xffffffffu, s,  o);
            s2 += __shfl_xor_sync(0xffffffffu, s2, o);
        }
        const float mean = s * (1.0f/DIN);
        const float var  = s2 * (1.0f/DIN) - mean*mean;
        const float rstd = rsqrtf(var + 1e-5f);
        for (int i = lane; i < DIN; i += 32)
            xn[rl*DIN + i] = (xr[i] - mean) * rstd * g[i] + be[i];
    }
    __syncthreads();

    if (tid < 192) {
        const float* W; float* dst; int col;
        if (tid < 64)       { W = seg==0 ? Wq : (seg==1 ? Wqs : Wqe); dst = g_Q; col = tid; }
        else if (tid < 128) { W = seg==0 ? Wk : (seg==1 ? Wks : Wke); dst = g_K; col = tid - 64; }
        else                { W = seg==0 ? Wv : (seg==1 ? Wvs : Wve); dst = g_V; col = tid - 128; }

        float acc[RPC];
        #pragma unroll
        for (int r = 0; r < RPC; r++) acc[r] = 0.f;

        for (int i4 = 0; i4 < DIN/4; i4++) {
            const int i = i4 * 4;
            const float w0 = W[(i+0)*DK + col];
            const float w1 = W[(i+1)*DK + col];
            const float w2 = W[(i+2)*DK + col];
            const float w3 = W[(i+3)*DK + col];
            #pragma unroll
            for (int r = 0; r < RPC; r++) {
                const float4 x4 = *(const float4*)&xn[r*DIN + i];
                acc[r] += x4.x*w0 + x4.y*w1 + x4.z*w2 + x4.w*w3;
            }
        }
        #pragma unroll
        for (int r = 0; r < RPC; r++) dst[(size_t)(r0 + r)*DK + col] = acc[r];
    }
}

// ---------------------------------------------------------------------------
// Kernel 2: fused CoPE-gated causal attention.
//  - CTA 32 q rows, 8 warps, 4 rows/warp. Heavy-first CTA order.
//  - Phase 1 (mid CTAs): 32-k tiles DESCENDING, gate suffix-sum, prefetch
//    pipeline, until CTA saturation vote (then bias == c127 exactly).
//  - Phase 2: ascending 64-key tiles, lean body, prefetch pipeline.
//  - PV with lane-split key-halves: lanes 0-15 take the low half of keys,
//    lanes 16-31 the high half; each lane covers 4 dims via float4 V reads.
//    Halves merged once at the end via shfl_xor(16). PV LDS halved.
//  - K tiles XOR-swizzled (d4 ^ ((row&7)<<2)); P half-2 XOR-swizzled (^4).
//    SMEM exactly 48 KB static.
// ---------------------------------------------------------------------------
#define KSWZ(row, d4w) (((row)*64) + ((d4w) ^ (((row)&7)<<2)))
__global__ __launch_bounds__(256, 2) void attn_kernel(
    const float* __restrict__ cope,   // [64][128] row-major
    float* __restrict__ out)          // [B][L][64]
{
    // 12288 floats = 49152 B exactly
    __shared__ __align__(16) float smemu[12288];
    float* const K2  = smemu;            // phase2 K: 64x64 swizzled  [0,4096)
    float* const V2  = smemu + 4096;     // phase2 V: 64x64           [4096,8192)
    float* const Csm = smemu;            // phase1 alias: 32x128      [0,4096)
    float* const K1  = smemu + 4096;     // phase1 K: 32x64 swizzled  [4096,6144)
    float* const V1  = smemu + 6144;     // phase1 V: 32x64           [6144,8192)
    float* const Psm = smemu + 8192;     // prob strips: 8 warps x 256 [8192,10240)
    float* const Qs  = smemu + 10240;    // 32x64                      [10240,12288)

    const int tid  = threadIdx.x;
    const int w    = tid >> 5;
    const int lane = tid & 31;
    const int lh   = lane >> 4;          // key-half for PV (0 or 1)
    const int lidx4 = (lane & 15) << 2;  // dim group for PV (float4)
    const int b    = blockIdx.y;
    const int q0   = (gridDim.x - 1 - blockIdx.x) * 32;   // heavy-first
    const int bL   = b * LL;
    const bool midq = (q0 >= MIDLO) && (q0 < MIDHI);
    const int wq0l  = w * 4;
    const int wq0g  = q0 + wq0l;
    const int qg3   = wq0g + 3;
    const int qmaxc = q0 + 31;
    const int pw    = w * 256;           // this warp's Psm base (words)

    // Load Q tile (32x64 floats = 512 float4)
    for (int i = tid; i < 512; i += 256) {
        const int row = i >> 4, d4q = (i & 15) << 2;
        *(float4*)&Qs[row*DK + d4q] =
            *(const float4*)&g_Q[(size_t)(bL + q0 + row)*DK + d4q];
    }
    __syncthreads();

    // CoPE logits: Csm[r][j] = q_r . cope[:, j];  c127 = saturated bias
    float c127[4] = {0.f,0.f,0.f,0.f};
    if (midq) {
        float4 ca[4] = {{0,0,0,0},{0,0,0,0},{0,0,0,0},{0,0,0,0}};
        const int j4 = lane * 4;
        #pragma unroll 4
        for (int d = 0; d < DK; d++) {
            const float4 cv = *(const float4*)&cope[d*SS + j4];
            #pragma unroll
            for (int r = 0; r < 4; r++) {
                const float qd = Qs[(wq0l + r)*DK + d];
                ca[r].x += qd*cv.x; ca[r].y += qd*cv.y;
                ca[r].z += qd*cv.z; ca[r].w += qd*cv.w;
            }
        }
        #pragma unroll
        for (int r = 0; r < 4; r++) {
            *(float4*)&Csm[(wq0l + r)*SS + j4] = ca[r];
            c127[r] = __shfl_sync(0xffffffffu, ca[r].w, 31);  // j=127 = lane31 .w
        }
    }

    float l[4]      = {0.f,0.f,0.f,0.f};
    float carry[4]  = {0.f,0.f,0.f,0.f};
    float acc[4][4] = {{0,0,0,0},{0,0,0,0},{0,0,0,0},{0,0,0,0}};  // [row][dim4]

    const int kkl   = 31 - lane;         // tile-local k, descending across lanes
    const int xswz  = (kkl & 7) << 2;    // K swizzle const for this lane
    const int t_cau = qmaxc >> 5;
    int t = midq ? (MIDHI/32 - 1) : t_cau;

    // ===== Phase 1: gate region (mid CTAs, 32-k tiles, prefetch pipeline) ====
    if (midq) {
        const int ld_row = tid >> 4;           // 0..15 -> rows ld_row, ld_row+16
        const int ld_d4  = (tid & 15) << 2;
        float4 kpf[2], vpf[2];
        if (t >= 0) {                          // prefetch first tile
            const int kb = t * 32;
            #pragma unroll
            for (int j = 0; j < 2; j++) {
                const int row = ld_row + j*16;
                kpf[j] = *(const float4*)&g_K[(size_t)(bL + kb + row)*DK + ld_d4];
                vpf[j] = *(const float4*)&g_V[(size_t)(bL + kb + row)*DK + ld_d4];
            }
        }

        for (; t >= 0; t--) {
            const bool wsat = (carry[0] >= 127.f) & (carry[1] >= 127.f) &
                              (carry[2] >= 127.f) & (carry[3] >= 127.f);
            if (__syncthreads_and(wsat)) break;   // vote doubles as SMEM fence

            const int  kb       = t * 32;
            const bool tile_mid = (kb >= MIDLO);

            // store prefetched tile t (K swizzled)
            #pragma unroll
            for (int j = 0; j < 2; j++) {
                const int row = ld_row + j*16;
                *(float4*)&K1[KSWZ(row, ld_d4)] = kpf[j];
                *(float4*)&V1[row*DK + ld_d4]   = vpf[j];
            }
            // prefetch tile t-1
            if (t - 1 >= 0) {
                const int kbn = kb - 32;
                #pragma unroll
                for (int j = 0; j < 2; j++) {
                    const int row = ld_row + j*16;
                    kpf[j] = *(const float4*)&g_K[(size_t)(bL + kbn + row)*DK + ld_d4];
                    vpf[j] = *(const float4*)&g_V[(size_t)(bL + kbn + row)*DK + ld_d4];
                }
            }
            __syncthreads();

            const bool anyw = (kb <= qg3);

            float dot[4] = {0.f,0.f,0.f,0.f};
            {
                const float* kbse = &K1[kkl*64];
                #pragma unroll 8
                for (int c = 0; c < 16; c++) {
                    const float4 kv = *(const float4*)&kbse[(4*c) ^ xswz];
                    #pragma unroll
                    for (int r = 0; r < 4; r++) {
                        const float4 qv = *(const float4*)&Qs[(wq0l + r)*DK + c*4];
                        dot[r] += kv.x*qv.x + kv.y*qv.y + kv.z*qv.z + kv.w*qv.w;
                    }
                }
            }

            if (anyw) {
                float pos[4] = {0.f,0.f,0.f,0.f};
                if (tile_mid) {
                    #pragma unroll
                    for (int r = 0; r < 4; r++) {
                        const float gg = __fdividef(1.f, 1.f + __expf(-dot[r]));
                        float pref = gg;
                        #pragma unroll
                        for (int o = 1; o < 32; o <<= 1) {
                            const float nv = __shfl_up_sync(0xffffffffu, pref, o);
                            if (lane >= o) pref += nv;
                        }
                        pos[r] = carry[r] + pref;
                        carry[r] += __shfl_sync(0xffffffffu, pref, 31);
                    }
                }

                const int kglob = kb + kkl;
                float p[4];
                #pragma unroll
                for (int r = 0; r < 4; r++) {
                    const int qr = wq0g + r;
                    float s = -1e30f;
                    if (kglob <= qr) {
                        s = dot[r] * SCALE;
                        if (tile_mid) {
                            const float pc  = fminf(pos[r], (float)(SS-1));
                            const float pf  = floorf(pc);
                            const int   ic  = (int)ceilf(pc);
                            const int   ifl = (int)pf;
                            const float wf  = pc - pf;
                            const float* cr = &Csm[(wq0l + r)*SS];
                            s += cr[ic]*wf + cr[ifl]*(1.f - wf);
                        }
                    }
                    p[r] = __expf(s);
                    l[r] += p[r];
                }

                // store p: key kkl; half split at 16, half2 bank-swizzled (^4)
                {
                    const int kh = kkl >> 4;
                    const int pa = pw + kh*64 + ((((kkl & 15) << 2)) ^ (kh << 2));
                    *(float4*)&Psm[pa] = make_float4(p[0], p[1], p[2], p[3]);
                }
                __syncwarp();
                // PV: lanes<16 -> keys 0..15, lanes>=16 -> keys 16..31; 4 dims/lane
                #pragma unroll 8
                for (int j = 0; j < 16; j++) {
                    const int pa = pw + lh*64 + ((j << 2) ^ (lh << 2));
                    const float4 pv = *(const float4*)&Psm[pa];
                    const int vrow = j + (lh << 4);
                    const float4 vv = *(const float4*)&V1[vrow*DK + lidx4];
                    acc[0][0] += pv.x*vv.x; acc[0][1] += pv.x*vv.y; acc[0][2] += pv.x*vv.z; acc[0][3] += pv.x*vv.w;
                    acc[1][0] += pv.y*vv.x; acc[1][1] += pv.y*vv.y; acc[1][2] += pv.y*vv.z; acc[1][3] += pv.y*vv.w;
                    acc[2][0] += pv.z*vv.x; acc[2][1] += pv.z*vv.y; acc[2][2] += pv.z*vv.z; acc[2][3] += pv.z*vv.w;
                    acc[3][0] += pv.w*vv.x; acc[3][1] += pv.w*vv.y; acc[3][2] += pv.w*vv.z; acc[3][3] += pv.w*vv.w;
                }
                __syncwarp();
            } else if (tile_mid) {
                // gate-only: tile SUM suffices for carry
                #pragma unroll
                for (int r = 0; r < 4; r++) {
                    float gg = __fdividef(1.f, 1.f + __expf(-dot[r]));
                    #pragma unroll
                    for (int o = 16; o; o >>= 1)
                        gg += __shfl_xor_sync(0xffffffffu, gg, o);
                    carry[r] += gg;
                }
            }
        }
    }

    // ===== Phase 2: ascending 64-key tiles, bias = c127, pipelined loads =====
    {
        const int hi  = (t < t_cau ? t : t_cau);
        const int n_k = (hi + 1) * 32;            // keys still to process
        const int ld_row0 = tid >> 4;             // 0..15
        const int ld_d4   = (tid & 15) << 2;

        float4 kf[4], vf[4];
        if (n_k > 0) {                            // prefetch block 0
            #pragma unroll
            for (int j = 0; j < 4; j++) {
                const int row = ld_row0 + j*16;
                if (row < n_k) {
                    kf[j] = *(const float4*)&g_K[(size_t)(bL + row)*DK + ld_d4];
                    vf[j] = *(const float4*)&g_V[(size_t)(bL + row)*DK + ld_d4];
                }
            }
        }

        for (int kb = 0; kb < n_k; kb += 64) {
            __syncthreads();                      // fence prior SMEM readers
            #pragma unroll
            for (int j = 0; j < 4; j++) {
                const int row = ld_row0 + j*16;
                const bool vld = (kb + row < n_k);
                *(float4*)&K2[KSWZ(row, ld_d4)] = kf[j];           // garbage OK (masked)
                *(float4*)&V2[row*DK + ld_d4]   = vld ? vf[j] : make_float4(0.f,0.f,0.f,0.f);
            }
            if (kb + 64 < n_k) {                  // prefetch next block
                #pragma unroll
                for (int j = 0; j < 4; j++) {
                    const int row = ld_row0 + j*16;
                    if (kb + 64 + row < n_k) {
                        kf[j] = *(const float4*)&g_K[(size_t)(bL + kb + 64 + row)*DK + ld_d4];
                        vf[j] = *(const float4*)&g_V[(size_t)(bL + kb + 64 + row)*DK + ld_d4];
                    }
                }
            }
            __syncthreads();

            if (kb <= qg3) {
                const bool biasOn = midq && (kb >= MIDLO);
                float dot[4]  = {0.f,0.f,0.f,0.f};
                float dot2[4] = {0.f,0.f,0.f,0.f};
                {
                    const float* kb1 = &K2[kkl*64];
                    const float* kb2 = &K2[(kkl+32)*64];
                    #pragma unroll 8
                    for (int c = 0; c < 16; c++) {
                        const float4 kv  = *(const float4*)&kb1[(4*c) ^ xswz];
                        const float4 kv2 = *(const float4*)&kb2[(4*c) ^ xswz];
                        #pragma unroll
                        for (int r = 0; r < 4; r++) {
                            const float4 qv = *(const float4*)&Qs[(wq0l + r)*DK + c*4];
                            dot[r]  += kv.x*qv.x  + kv.y*qv.y  + kv.z*qv.z  + kv.w*qv.w;
                            dot2[r] += kv2.x*qv.x + kv2.y*qv.y + kv2.z*qv.z + kv2.w*qv.w;
                        }
                    }
                }

                const int kglob  = kb + kkl;
                const int kglob2 = kglob + 32;
                float p[4], p2[4];
                #pragma unroll
                for (int r = 0; r < 4; r++) {
                    const int qr = wq0g + r;
                    float s = -1e30f, s2 = -1e30f;
                    if (kglob <= qr) {
                        s = dot[r] * SCALE;
                        if (biasOn) s += c127[r];
                    }
                    if (kglob2 <= qr && kglob2 < n_k) {
                        s2 = dot2[r] * SCALE;
                        if (biasOn) s2 += c127[r];
                    }
                    p[r]  = __expf(s);
                    p2[r] = __expf(s2);
                    l[r] += p[r] + p2[r];
                }

                // store p (key kkl) and p2 (key kkl+32, bank-swizzled half)
                *(float4*)&Psm[pw + (kkl << 2)]               = make_float4(p[0], p[1], p[2], p[3]);
                *(float4*)&Psm[pw + 128 + ((kkl << 2) ^ 4)]   = make_float4(p2[0], p2[1], p2[2], p2[3]);
                __syncwarp();
                // PV: lanes<16 -> keys kb..kb+31, lanes>=16 -> kb+32..kb+63
                #pragma unroll 8
                for (int j = 0; j < 32; j++) {
                    const int pa = pw + lh*128 + ((j << 2) ^ (lh << 2));
                    const float4 pv = *(const float4*)&Psm[pa];
                    const int vrow = j + (lh << 5);
                    const float4 vv = *(const float4*)&V2[vrow*DK + lidx4];
                    acc[0][0] += pv.x*vv.x; acc[0][1] += pv.x*vv.y; acc[0][2] += pv.x*vv.z; acc[0][3] += pv.x*vv.w;
                    acc[1][0] += pv.y*vv.x; acc[1][1] += pv.y*vv.y; acc[1][2] += pv.y*vv.z; acc[1][3] += pv.y*vv.w;
                    acc[2][0] += pv.z*vv.x; acc[2][1] += pv.z*vv.y; acc[2][2] += pv.z*vv.z; acc[2][3] += pv.z*vv.w;
                    acc[3][0] += pv.w*vv.x; acc[3][1] += pv.w*vv.y; acc[3][2] += pv.w*vv.z; acc[3][3] += pv.w*vv.w;
                }
                __syncwarp();
            }
        }
    }

    // Final: merge key-halves, reduce denominators, normalize, store.
    #pragma unroll
    for (int r = 0; r < 4; r++) {
        float lr = l[r];
        #pragma unroll
        for (int o = 16; o; o >>= 1) lr += __shfl_xor_sync(0xffffffffu, lr, o);
        const float inv = 1.f / lr;
        #pragma unroll
        for (int c = 0; c < 4; c++)
            acc[r][c] += __shfl_xor_sync(0xffffffffu, acc[r][c], 16);
        if (lane < 16) {
            float4 o4;
            o4.x = acc[r][0]*inv; o4.y = acc[r][1]*inv;
            o4.z = acc[r][2]*inv; o4.w = acc[r][3]*inv;
            *(float4*)&out[(size_t)(bL + wq0g + r)*DK + lidx4] = o4;
        }
    }
}

// ---------------------------------------------------------------------------
extern "C" void kernel_launch(void* const* d_in, const int* in_sizes, int n_in,
                              void* d_out, int out_size)
{
    const float* x    = (const float*)d_in[0];
    const float* Wq   = (const float*)d_in[1];
    const float* Wk   = (const float*)d_in[2];
    const float* Wv   = (const float*)d_in[3];
    const float* Wqs  = (const float*)d_in[4];
    const float* Wks  = (const float*)d_in[5];
    const float* Wvs  = (const float*)d_in[6];
    const float* Wqe  = (const float*)d_in[7];
    const float* Wke  = (const float*)d_in[8];
    const float* Wve  = (const float*)d_in[9];
    const float* lg   = (const float*)d_in[10];
    const float* lb   = (const float*)d_in[11];
    const float* lsg  = (const float*)d_in[12];
    const float* lsb  = (const float*)d_in[13];
    const float* leg  = (const float*)d_in[14];
    const float* leb  = (const float*)d_in[15];
    const float* cope = (const float*)d_in[16];
    float* out = (float*)d_out;

    ln_proj_kernel<<<NROW/RPC, 256>>>(x, Wq, Wk, Wv, Wqs, Wks, Wvs, Wqe, Wke, Wve,
                                      lg, lb, lsg, lsb, leg, leb);
    attn_kernel<<<dim3(LL/32, BB), 256>>>(cope, out);
}